// round 5
// baseline (speedup 1.0000x reference)
#include <cuda_runtime.h>
#include <cuda_fp16.h>
#include <cstdint>

// ===================== scratch (no allocations allowed) =====================
__device__ __align__(16) __half   g_xw[8192u * 512u];     // 8 MB  xw[n][o]
__device__ __align__(16) uint32_t g_xbits[8192u * 16u];   // x>0 bitplanes
__device__ __align__(16) uint32_t g_wp[512u * 16u];       // w>0 bits
__device__ __align__(16) uint32_t g_wn[512u * 16u];       // w<0 bits

#define SW128(x) ((x) ^ ((((uint32_t)(x)) >> 3) & 0x70u))

__device__ __forceinline__ uint32_t smem_u32(const void* p) {
    uint32_t a;
    asm("{ .reg .u64 t; cvta.to.shared.u64 t, %1; cvt.u32.u64 %0, t; }" : "=r"(a) : "l"(p));
    return a;
}

// ============================================================================
// pack_x: bit-pack (x > 0): one warp per row of 512
// ============================================================================
__global__ void __launch_bounds__(256)
pack_x(const float* __restrict__ x) {
    const int warp = (blockIdx.x * blockDim.x + threadIdx.x) >> 5;
    const int lane = threadIdx.x & 31;
    const float* row = x + (size_t)warp * 512;
    #pragma unroll
    for (int c = 0; c < 16; ++c) {
        float v = row[c * 32 + lane];
        unsigned b = __ballot_sync(0xffffffffu, v > 0.f);
        if (lane == c) g_xbits[warp * 16 + c] = b;   // lane==c: one writer per c
    }
}

// pack_w: bit-pack sign planes of weight: one warp per row of 512
__global__ void __launch_bounds__(256)
pack_w(const float* __restrict__ w) {
    const int warp = (blockIdx.x * blockDim.x + threadIdx.x) >> 5;
    const int lane = threadIdx.x & 31;
    const float* row = w + (size_t)warp * 512;
    #pragma unroll
    for (int c = 0; c < 16; ++c) {
        float v = row[c * 32 + lane];
        unsigned bp = __ballot_sync(0xffffffffu, v > 0.f);
        unsigned bn = __ballot_sync(0xffffffffu, v < 0.f);
        if (lane == c) { g_wp[warp * 16 + c] = bp; g_wn[warp * 16 + c] = bn; }
    }
}

// ============================================================================
// k1_popc: xw[n][o] = popc(xb & wp) - popc(xb & wn), fp16 out
// block: 64 n-rows x 512 o; 256 threads, each owns o = tid and tid+256
// ============================================================================
__global__ void __launch_bounds__(256, 1)
k1_popc() {
    extern __shared__ uint32_t sh[];                   // wp[512*16] wn[512*16] xb[64*16]
    uint32_t* swp = sh;
    uint32_t* swn = sh + 512 * 16;
    uint32_t* sxb = sh + 2 * 512 * 16;
    const int tid = threadIdx.x;
    const int nb = blockIdx.x * 64;

    for (int i = tid; i < 2048; i += 256) {            // 512*16/4 uint4 per array
        ((uint4*)swp)[i] = ((const uint4*)g_wp)[i];
        ((uint4*)swn)[i] = ((const uint4*)g_wn)[i];
    }
    ((uint4*)sxb)[tid] = ((const uint4*)(g_xbits + (size_t)nb * 16))[tid];  // 256 uint4
    __syncthreads();

    uint32_t wpA[16], wnA[16], wpB[16], wnB[16];
    #pragma unroll
    for (int c = 0; c < 16; ++c) {
        wpA[c] = swp[tid * 16 + c];          wnA[c] = swn[tid * 16 + c];
        wpB[c] = swp[(tid + 256) * 16 + c];  wnB[c] = swn[(tid + 256) * 16 + c];
    }

    for (int n = 0; n < 64; ++n) {
        uint32_t xb[16];
        #pragma unroll
        for (int q = 0; q < 4; ++q) {
            uint4 v = ((const uint4*)(sxb + n * 16))[q];   // smem broadcast
            xb[q*4+0] = v.x; xb[q*4+1] = v.y; xb[q*4+2] = v.z; xb[q*4+3] = v.w;
        }
        int pa = 0, qa = 0, pb = 0, qb = 0;
        #pragma unroll
        for (int c = 0; c < 16; ++c) {
            pa += __popc(xb[c] & wpA[c]);  qa += __popc(xb[c] & wnA[c]);
            pb += __popc(xb[c] & wpB[c]);  qb += __popc(xb[c] & wnB[c]);
        }
        __half* dst = g_xw + (size_t)(nb + n) * 512;
        dst[tid]       = __float2half_rn((float)(pa - qa));
        dst[tid + 256] = __float2half_rn((float)(pb - qb));
    }
}

// ============================================================================
// k2: out = relu(support @ xw)   M=8192 N=512 K=8192
// CTA: 256 thr, tile 128x256, KB=64, warp tile 64x64 (2x4 warps)
// A: f32 LDG -> cvt f16 -> SW128 smem ; B: cp.async f16 (xor-swizzled rows)
// mma.sync.m16n8k16 f16 -> f32 acc ; fused relu epilogue -> d_out
// ============================================================================
constexpr uint32_t K2_A_STAGE = 16384;                 // 128 rows x 128B
constexpr uint32_t K2_B_STAGE = 32768;                 // 64 rows x 512B
constexpr uint32_t K2_OFF_B   = 2 * K2_A_STAGE;        // 32768
constexpr uint32_t K2_SMEM    = K2_OFF_B + 2 * K2_B_STAGE;   // 98304

__global__ void __launch_bounds__(256, 1)
k2_support_gemm(const float* __restrict__ support, float* __restrict__ out) {
    extern __shared__ char smem[];
    const uint32_t sb = smem_u32(smem);
    const int tid  = threadIdx.x;
    const int wid  = tid >> 5;
    const int lane = tid & 31;
    const int wm = wid >> 2;           // 0..1 -> m offset wm*64
    const int wn = wid & 3;            // 0..3 -> n offset wn*64
    const int m0 = blockIdx.x * 128;
    const int n0 = blockIdx.y * 256;

    // ---- per-thread load mappings (loop-invariant) ----
    const int arow = tid >> 4;              // + 16*p
    const int acol = tid & 15;              // float4 col within KB=64
    const int bk   = tid >> 5;              // + 8*p
    const int bc   = tid & 31;              // 16B block col
    const float* Ag = support + (size_t)(m0 + arow) * 8192 + acol * 4;
    const __half* Bg = g_xw + (size_t)bk * 512 + n0 + bc * 8;

    uint32_t aSts[8], bDst[8];
    #pragma unroll
    for (int p = 0; p < 8; ++p) {
        aSts[p] = sb + SW128((uint32_t)((arow + 16 * p) * 128 + acol * 8));
        const int k = bk + 8 * p;
        bDst[p] = sb + K2_OFF_B + (uint32_t)(k * 512 + (((bc) ^ (k & 7)) << 4));
    }

    const int lrow = lane & 15;             // ldmatrix row within 16
    const int lhi  = lane >> 4;             // ldmatrix 16B-block parity

    float acc[4][8][4];
    #pragma unroll
    for (int i = 0; i < 4; ++i)
        #pragma unroll
        for (int j = 0; j < 8; ++j)
            #pragma unroll
            for (int r = 0; r < 4; ++r) acc[i][j][r] = 0.f;

    float4 aReg[8];

    auto loadA = [&](int kk) {
        #pragma unroll
        for (int p = 0; p < 8; ++p)
            aReg[p] = *(const float4*)(Ag + (size_t)p * 16 * 8192 + kk);
    };
    auto stsA = [&](int s) {
        #pragma unroll
        for (int p = 0; p < 8; ++p) {
            __half2 h0 = __float22half2_rn(make_float2(aReg[p].x, aReg[p].y));
            __half2 h1 = __float22half2_rn(make_float2(aReg[p].z, aReg[p].w));
            uint2 u;
            u.x = *reinterpret_cast<uint32_t*>(&h0);
            u.y = *reinterpret_cast<uint32_t*>(&h1);
            asm volatile("st.shared.v2.b32 [%0], {%1, %2};"
                         :: "r"(aSts[p] + s * K2_A_STAGE), "r"(u.x), "r"(u.y) : "memory");
        }
    };
    auto cpB = [&](int kk, int s) {
        #pragma unroll
        for (int p = 0; p < 8; ++p) {
            const __half* src = Bg + (size_t)(kk + 8 * p) * 512;
            asm volatile("cp.async.cg.shared.global [%0], [%1], 16;"
                         :: "r"(bDst[p] + s * K2_B_STAGE), "l"(src) : "memory");
        }
    };

    auto compute = [&](int s) {
        const uint32_t abase = sb + s * K2_A_STAGE;
        const uint32_t bbase = sb + K2_OFF_B + s * K2_B_STAGE;
        #pragma unroll
        for (int kf = 0; kf < 4; ++kf) {
            uint32_t a[4][4], b[4][4];
            #pragma unroll
            for (int mf = 0; mf < 4; ++mf) {
                uint32_t addr = abase + SW128((uint32_t)((wm * 64 + mf * 16 + lrow) * 128
                                                         + (kf * 2 + lhi) * 16));
                asm volatile("ldmatrix.sync.aligned.m8n8.x4.shared.b16 {%0,%1,%2,%3}, [%4];"
                             : "=r"(a[mf][0]), "=r"(a[mf][1]), "=r"(a[mf][2]), "=r"(a[mf][3])
                             : "r"(addr));
            }
            const int kr = kf * 16 + lrow;
            #pragma unroll
            for (int nf = 0; nf < 4; ++nf) {
                const int c = wn * 8 + nf * 2 + lhi;
                uint32_t addr = bbase + (uint32_t)(kr * 512 + (((c) ^ (kr & 7)) << 4));
                asm volatile("ldmatrix.sync.aligned.m8n8.x4.trans.shared.b16 {%0,%1,%2,%3}, [%4];"
                             : "=r"(b[nf][0]), "=r"(b[nf][1]), "=r"(b[nf][2]), "=r"(b[nf][3])
                             : "r"(addr));
            }
            #pragma unroll
            for (int mf = 0; mf < 4; ++mf)
                #pragma unroll
                for (int nf = 0; nf < 8; ++nf) {
                    const uint32_t b0 = b[nf >> 1][(nf & 1) * 2];
                    const uint32_t b1 = b[nf >> 1][(nf & 1) * 2 + 1];
                    asm volatile(
                        "mma.sync.aligned.m16n8k16.row.col.f32.f16.f16.f32 "
                        "{%0,%1,%2,%3}, {%4,%5,%6,%7}, {%8,%9}, {%0,%1,%2,%3};"
                        : "+f"(acc[mf][nf][0]), "+f"(acc[mf][nf][1]),
                          "+f"(acc[mf][nf][2]), "+f"(acc[mf][nf][3])
                        : "r"(a[mf][0]), "r"(a[mf][1]), "r"(a[mf][2]), "r"(a[mf][3]),
                          "r"(b0), "r"(b1));
                }
        }
    };

    // ---- prologue ----
    cpB(0, 0);
    asm volatile("cp.async.commit_group;" ::: "memory");
    loadA(0);
    stsA(0);
    asm volatile("cp.async.wait_group 0;" ::: "memory");
    __syncthreads();

    // ---- main loop: 128 k-steps ----
    for (int it = 0; it < 128; ++it) {
        const int s = it & 1;
        const bool more = (it + 1) < 128;
        if (more) {
            cpB((it + 1) * 64, s ^ 1);
            asm volatile("cp.async.commit_group;" ::: "memory");
            loadA((it + 1) * 64);
        }
        compute(s);
        if (more) {
            stsA(s ^ 1);
            asm volatile("cp.async.wait_group 0;" ::: "memory");
        }
        __syncthreads();
    }

    // ---- epilogue: relu -> d_out ----
    const int rbase = m0 + wm * 64 + (lane >> 2);
    const int cbase = n0 + wn * 64 + 2 * (lane & 3);
    #pragma unroll
    for (int mf = 0; mf < 4; ++mf)
        #pragma unroll
        for (int nf = 0; nf < 8; ++nf) {
            const int r = rbase + mf * 16;
            const int c = cbase + nf * 8;
            float2 v0 = make_float2(fmaxf(acc[mf][nf][0], 0.f), fmaxf(acc[mf][nf][1], 0.f));
            float2 v1 = make_float2(fmaxf(acc[mf][nf][2], 0.f), fmaxf(acc[mf][nf][3], 0.f));
            *(float2*)(out + (size_t)r * 512 + c)       = v0;
            *(float2*)(out + (size_t)(r + 8) * 512 + c) = v1;
        }
}

// ============================================================================
extern "C" void kernel_launch(void* const* d_in, const int* in_sizes, int n_in,
                              void* d_out, int out_size) {
    // Resolve inputs by element count, with positional fallback (x, support, weight).
    const float* x = nullptr;
    const float* support = nullptr;
    const float* weight = nullptr;
    for (int i = 0; i < n_in; ++i) {
        if (in_sizes[i] == 4194304)       x       = (const float*)d_in[i];
        else if (in_sizes[i] == 67108864) support = (const float*)d_in[i];
        else if (in_sizes[i] == 262144)   weight  = (const float*)d_in[i];
    }
    if (!x && n_in > 0)       x       = (const float*)d_in[0];
    if (!support && n_in > 1) support = (const float*)d_in[1];
    if (!weight && n_in > 2)  weight  = (const float*)d_in[2];
    float* out = (float*)d_out;

    cudaFuncSetAttribute(k1_popc, cudaFuncAttributeMaxDynamicSharedMemorySize, 69632);
    cudaFuncSetAttribute(k2_support_gemm, cudaFuncAttributeMaxDynamicSharedMemorySize, K2_SMEM);

    pack_x<<<1024, 256>>>(x);                       // 8192 rows, 8 warps/block
    pack_w<<<64, 256>>>(weight);                    // 512 rows
    k1_popc<<<128, 256, 69632>>>();                 // xw fp16 [8192][512]
    k2_support_gemm<<<dim3(64, 2), 256, K2_SMEM>>>(support, out);
}